// round 16
// baseline (speedup 1.0000x reference)
#include <cuda_runtime.h>
#include <cuda_fp16.h>
#include <cooperative_groups.h>
#include <math.h>

namespace cg = cooperative_groups;

#define BATCH   64
#define T_IN    104
#define NFEAT   20
#define NPEMB   64
#define NCOND   256
#define NSUB    40
#define NSTEPS  400
#define NBF     100

#define RANKS   4
#define BPC     4
#define RCOLS   64

typedef unsigned long long u64;

// ---------------- device scratch ----------------
static __device__ float g_t   [BATCH * T_IN * NCOND];
static __device__ float g_cond[BATCH * NBF  * NCOND];
static __device__ float g_pre [BATCH * NSTEPS * NSUB];
static __device__ float g_pim [BATCH * NSTEPS * NSUB];
static __device__ float g_w1t [NCOND * 3 * NCOND];
static __device__ float g_w2t [NCOND * 3 * NCOND];
static __device__ __half g_sd1h[376 * NCOND];
static __device__ __half g_sd2h[NCOND * NCOND];
static __device__ __half g_gw[6][NCOND * 768];

__device__ __forceinline__ float sigm(float x) { return 1.0f / (1.0f + expf(-x)); }

// ---- packed f32x2 helpers ----
__device__ __forceinline__ u64 bcast2(float a) {
    u64 r; asm("mov.b64 %0, {%1, %1};" : "=l"(r) : "f"(a)); return r;
}
__device__ __forceinline__ void fma2(u64& d, u64 a, u64 b) {
    asm("fma.rn.f32x2 %0, %1, %2, %0;" : "+l"(d) : "l"(a), "l"(b));
}

// ---------------- prep: fp16 weights + conv transpose + phase embedding ----------------
__global__ void prep_kernel(const int* __restrict__ period, const float* __restrict__ rshift,
                            const float* __restrict__ sd1, const float* __restrict__ sd2,
                            const float* __restrict__ a0, const float* __restrict__ a1,
                            const float* __restrict__ a2, const float* __restrict__ a3,
                            const float* __restrict__ a4, const float* __restrict__ a5,
                            const float* __restrict__ c1w, const float* __restrict__ c2w) {
    if (blockIdx.x < 64) {
        const float TWOPI = 6.28318530717958647692f;
        int b = blockIdx.x;
        __shared__ float s_cum[NBF], s_w0[NBF];
        if (threadIdx.x == 0) {
            float acc = TWOPI * rshift[b] / 160.0f;
            for (int f = 0; f < NBF; f++) {
                float w0 = TWOPI / (float)period[b * T_IN + 3 + f];
                s_w0[f] = w0; s_cum[f] = 160.0f * acc; acc += w0;
            }
        }
        __syncthreads();
        float* pre = g_pre + (size_t)b * NSTEPS * NSUB;
        float* pim = g_pim + (size_t)b * NSTEPS * NSUB;
        for (int idx = threadIdx.x; idx < NSTEPS * NSUB; idx += blockDim.x) {
            int s = idx / NSUB, j = idx - s * NSUB;
            float e = s_cum[s >> 2] + s_w0[s >> 2] * (float)((s & 3) * NSUB + j);
            double sv, cv; sincos((double)e, &sv, &cv);
            pre[idx] = (float)cv; pim[idx] = (float)sv;
        }
        return;
    }
    int i = (blockIdx.x - 64) * 256 + threadIdx.x;
    if (i < 376 * NCOND)   g_sd1h[i] = __float2half_rn(sd1[i]);
    if (i < NCOND * NCOND) g_sd2h[i] = __float2half_rn(sd2[i]);
    if (i < NCOND * 768) {
        g_gw[0][i] = __float2half_rn(a0[i]); g_gw[1][i] = __float2half_rn(a1[i]);
        g_gw[2][i] = __float2half_rn(a2[i]); g_gw[3][i] = __float2half_rn(a3[i]);
        g_gw[4][i] = __float2half_rn(a4[i]); g_gw[5][i] = __float2half_rn(a5[i]);
    }
    if (i < NCOND * NCOND * 3) {
        int o = i / (NCOND * 3), r = i - o * (NCOND * 3);
        g_w1t[r * NCOND + o] = c1w[i];
        g_w2t[r * NCOND + o] = c2w[i];
    }
}

// ---------------- fd1 ----------------
__global__ void fd1_kernel(const float* __restrict__ feat, const int* __restrict__ period,
                           const float* __restrict__ pemb, const float* __restrict__ w,
                           const float* __restrict__ bias) {
    int bt = blockIdx.x, tid = threadIdx.x;
    __shared__ float xs[NFEAT + NPEMB];
    if (tid < NFEAT)              xs[tid] = feat[(size_t)bt * NFEAT + tid];
    else if (tid < NFEAT + NPEMB) xs[tid] = pemb[(size_t)period[bt] * NPEMB + (tid - NFEAT)];
    __syncthreads();
    float acc = bias[tid];
#pragma unroll 4
    for (int k = 0; k < NFEAT + NPEMB; k++)
        acc = fmaf(xs[k], w[(size_t)k * NCOND + tid], acc);
    g_t[(size_t)bt * NCOND + tid] = tanhf(acc);
}

// ---------------- cond2: fused conv1+conv2+fd2 ----------------
__global__ void cond2_kernel(const float* __restrict__ c1b, const float* __restrict__ c2b,
                             const float* __restrict__ fd2w, const float* __restrict__ fd2b) {
    int bf = blockIdx.x;
    int b = bf / NBF, f = bf - b * NBF;
    int tid = threadIdx.x;
    __shared__ float xs[5][NCOND], c1s[3][NCOND], c2s[NCOND];
#pragma unroll
    for (int d = 0; d < 5; d++)
        xs[d][tid] = g_t[((size_t)(b * T_IN + f + d)) * NCOND + tid];
    __syncthreads();
    float a0 = c1b[tid], a1 = a0, a2 = a0;
    for (int i = 0; i < NCOND; i++) {
#pragma unroll
        for (int d = 0; d < 3; d++) {
            float w = g_w1t[(size_t)(i * 3 + d) * NCOND + tid];
            a0 = fmaf(xs[d][i],     w, a0);
            a1 = fmaf(xs[d + 1][i], w, a1);
            a2 = fmaf(xs[d + 2][i], w, a2);
        }
    }
    c1s[0][tid] = tanhf(a0); c1s[1][tid] = tanhf(a1); c1s[2][tid] = tanhf(a2);
    __syncthreads();
    float acc = c2b[tid];
    for (int i = 0; i < NCOND; i++) {
#pragma unroll
        for (int d = 0; d < 3; d++)
            acc = fmaf(c1s[d][i], g_w2t[(size_t)(i * 3 + d) * NCOND + tid], acc);
    }
    c2s[tid] = tanhf(acc);
    __syncthreads();
    acc = fd2b[tid];
#pragma unroll 4
    for (int k = 0; k < NCOND; k++)
        acc = fmaf(c2s[k], fd2w[(size_t)k * NCOND + tid], acc);
    g_cond[(size_t)bf * NCOND + tid] = tanhf(acc);
}

// ======================= rnn: cluster-4, 4-batch, fp16 weights, FFMA2 =================
// 16 clusters x 4 CTAs (64 SMs). Rank r owns cols [64r,64r+64). R13's exact
// 6-phase skeleton (sd1, sd2, gru1-3, out) with cluster.sync; each weight is
// loaded once (half2) and FMA2'd against 4 batch rows. Activations [k][b0..b3]
// so LDS.128 yields two f32x2 pairs. Hidden states double-buffered by parity.
struct RS {
    float part[768 * 8];       // 24576 B: per-thread {c0b01,c0b23,c1b01,c1b23}
    float x2 [376 * BPC];      // 6016: [k][b]  cond|prev|pr|pi
    float tta[NCOND * BPC];    // 4096
    float ttb[NCOND * BPC];    // 4096
    float h  [3][2][NCOND * BPC]; // 24576: [layer][parity][col][b]
    float gil[3][RCOLS * BPC]; // 3072
    float ghl[3][RCOLS * BPC]; // 3072
};                             // 69504 B (dynamic)

// sd layer: this rank's 64 cols x 4 batch. 32 col-pairs (lane) x 24 K-splits (warp).
__device__ __forceinline__ void sd_phase(
    const __half* __restrict__ W, const float* __restrict__ B,
    const float* x, int K, int kper, int dst_off,
    RS* sm, float* const* rb, cg::cluster_group& cl, int rank, int tid)
{
    int lane = tid & 31, ks = tid >> 5;
    const __half* Wp = W + RCOLS * rank + 2 * lane;
    u64 a0 = 0, a1 = 0, a2 = 0, a3 = 0;
    int k0 = ks * kper, k1 = k0 + kper; if (k1 > K) k1 = K;
#pragma unroll 4
    for (int k = k0; k < k1; k++) {
        float2 wf = __half22float2(*(const __half2*)(Wp + (size_t)k * NCOND));
        u64 w0 = bcast2(wf.x), w1 = bcast2(wf.y);
        ulonglong2 xx = *(const ulonglong2*)(x + 4 * k);
        fma2(a0, w0, xx.x); fma2(a1, w0, xx.y);
        fma2(a2, w1, xx.x); fma2(a3, w1, xx.y);
    }
    u64* pp = (u64*)(sm->part + tid * 8);
    pp[0] = a0; pp[1] = a1; pp[2] = a2; pp[3] = a3;
    __syncthreads();
    if (tid < 256) {
        int b = tid & 3, l64 = tid >> 2;
        int pr = l64 >> 1, comp = (l64 & 1) * 4 + b;
        float s = 0.f;
#pragma unroll
        for (int j = 0; j < 24; j++) s += sm->part[(j * 32 + pr) * 8 + comp];
        float v = tanhf(s + B[RCOLS * rank + l64]);
        int di = dst_off + (RCOLS * rank + l64) * BPC + b;
#pragma unroll
        for (int r = 0; r < RANKS; r++) rb[r][di] = v;
    }
    cl.sync();
}

// GRU layer: 24 warps = (gi/gh) x (gate t) x (4 K-splits); 32 col-pairs per warp.
__device__ __forceinline__ void gru_layer(
    const __half* __restrict__ wi, const float* __restrict__ bi,
    const __half* __restrict__ wh, const float* __restrict__ bh,
    const float* xv, const float* hold, int hnew_off,
    RS* sm, float* const* rb, cg::cluster_group& cl, int rank, int tid)
{
    {
        int wid = tid >> 5, lane = tid & 31;
        int hf = wid >= 12 ? 1 : 0;
        int w12 = wid - 12 * hf;
        int t = w12 >> 2, ks = w12 & 3;
        const __half* Wp = (hf ? wh : wi) + 256 * t + RCOLS * rank + 2 * lane;
        const float* v = hf ? hold : xv;
        u64 a0 = 0, a1 = 0, a2 = 0, a3 = 0;
        int k0 = ks * 64;
#pragma unroll 4
        for (int k = k0; k < k0 + 64; k++) {
            float2 wf = __half22float2(*(const __half2*)(Wp + (size_t)k * 768));
            u64 w0 = bcast2(wf.x), w1 = bcast2(wf.y);
            ulonglong2 xx = *(const ulonglong2*)(v + 4 * k);
            fma2(a0, w0, xx.x); fma2(a1, w0, xx.y);
            fma2(a2, w1, xx.x); fma2(a3, w1, xx.y);
        }
        u64* pp = (u64*)(sm->part + tid * 8);
        pp[0] = a0; pp[1] = a1; pp[2] = a2; pp[3] = a3;
    }
    __syncthreads();
    for (int e = tid; e < 1536; e += 768) {    // (hf, gate, col, b) entries
        int b = e & 3, r2 = e >> 2;            // r2: hf*192 + t*64 + l64
        int l64 = r2 & 63, t = (r2 >> 6) % 3, hf = r2 / 192;
        int pr = l64 >> 1, comp = (l64 & 1) * 4 + b;
        int wbase = hf * 12 + t * 4;
        float s = sm->part[((wbase + 0) * 32 + pr) * 8 + comp]
                + sm->part[((wbase + 1) * 32 + pr) * 8 + comp]
                + sm->part[((wbase + 2) * 32 + pr) * 8 + comp]
                + sm->part[((wbase + 3) * 32 + pr) * 8 + comp];
        s += (hf ? bh : bi)[256 * t + RCOLS * rank + l64];
        (hf ? sm->ghl : sm->gil)[t][l64 * BPC + b] = s;
    }
    __syncthreads();
    if (tid < 256) {
        int b = tid & 3, l64 = tid >> 2;
        int li = l64 * BPC + b;
        int ci = (RCOLS * rank + l64) * BPC + b;
        float rg = sigm(sm->gil[0][li] + sm->ghl[0][li]);
        float zg = sigm(sm->gil[1][li] + sm->ghl[1][li]);
        float ng = tanhf(fmaf(rg, sm->ghl[2][li], sm->gil[2][li]));
        float hv = fmaf(zg, hold[ci] - ng, ng);
        int di = hnew_off + ci;
#pragma unroll
        for (int r = 0; r < RANKS; r++) rb[r][di] = hv;
    }
    cl.sync();
}

__global__ void __cluster_dims__(RANKS, 1, 1) __launch_bounds__(768, 1) rnn_kernel(
    const float* __restrict__ sd1_b, const float* __restrict__ sd2_b,
    const float* __restrict__ g1_bi, const float* __restrict__ g1_bh,
    const float* __restrict__ g2_bi, const float* __restrict__ g2_bh,
    const float* __restrict__ g3_bi, const float* __restrict__ g3_bh,
    const float* __restrict__ out_w, const float* __restrict__ out_b,
    float* __restrict__ d_sig, float* __restrict__ d_h, int write_h)
{
    extern __shared__ char smraw[];
    RS* sm = (RS*)smraw;
    cg::cluster_group cl = cg::this_cluster();
    const int rank = (int)cl.block_rank();
    const int b0   = (blockIdx.x / RANKS) * BPC;
    const int tid  = threadIdx.x;

    float* base = (float*)sm;
    float* rb[RANKS];
#pragma unroll
    for (int r = 0; r < RANKS; r++) rb[r] = (float*)cl.map_shared_rank(sm, r);
    const int OFF_X  = (int)(sm->x2  - base);
    const int OFF_TA = (int)(sm->tta - base);
    const int OFF_TB = (int)(sm->ttb - base);
    const int OFF_H  = (int)(&sm->h[0][0][0] - base);
    const int HB_L   = 2 * NCOND * BPC;
    const int HB_P   = NCOND * BPC;

    for (int i = tid; i < 3 * 2 * NCOND * BPC; i += 768) (&sm->h[0][0][0])[i] = 0.f;
    for (int i = tid; i < NSUB * BPC; i += 768) sm->x2[256 * BPC + i] = 0.f;
    cl.sync();

    for (int s = 0; s < NSTEPS; s++) {
        const int p = s & 1;
        for (int i = tid; i < 256 * BPC; i += 768) {
            int b = i & 3, c = i >> 2;
            sm->x2[c * BPC + b] = g_cond[((size_t)(b0 + b) * NBF + (s >> 2)) * NCOND + c];
        }
        for (int i = tid; i < 80 * BPC; i += 768) {
            int b = i & 3, j = i >> 2;
            sm->x2[(296 + j) * BPC + b] = (j < NSUB)
                ? g_pre[(size_t)(b0 + b) * NSTEPS * NSUB + s * NSUB + j]
                : g_pim[(size_t)(b0 + b) * NSTEPS * NSUB + s * NSUB + (j - NSUB)];
        }
        __syncthreads();

        sd_phase(g_sd1h, sd1_b, sm->x2,  376, 16, OFF_TA, sm, rb, cl, rank, tid);
        sd_phase(g_sd2h, sd2_b, sm->tta, 256, 11, OFF_TB, sm, rb, cl, rank, tid);

        gru_layer(g_gw[0], g1_bi, g_gw[1], g1_bh, sm->ttb,            sm->h[0][p],
                  OFF_H + 0 * HB_L + (p ^ 1) * HB_P, sm, rb, cl, rank, tid);
        gru_layer(g_gw[2], g2_bi, g_gw[3], g2_bh, sm->h[0][p ^ 1],    sm->h[1][p],
                  OFF_H + 1 * HB_L + (p ^ 1) * HB_P, sm, rb, cl, rank, tid);
        gru_layer(g_gw[4], g3_bi, g_gw[5], g3_bh, sm->h[1][p ^ 1],    sm->h[2][p],
                  OFF_H + 2 * HB_L + (p ^ 1) * HB_P, sm, rb, cl, rank, tid);

        // out layer: this rank's 10 cols x 4 batch; 16 K-splits
        const float* h3 = sm->h[2][p ^ 1];
        if (tid < 640) {
            int b = tid & 3, r2 = tid >> 2;      // r2: ks*10 + c
            int c = r2 % 10, ks = r2 / 10;
            const float* Wp = out_w + 10 * rank + c;
            float a = 0.f;
            int k0 = ks * 16;
#pragma unroll
            for (int k = k0; k < k0 + 16; k++)
                a = fmaf(Wp[k * NSUB], h3[k * BPC + b], a);
            sm->part[tid] = a;
        }
        __syncthreads();
        if (tid < 40) {
            int b = tid & 3, c = tid >> 2;
            float sacc = 0.f;
#pragma unroll
            for (int ks = 0; ks < 16; ks++) sacc += sm->part[(ks * 10 + c) * 4 + b];
            int gcol = 10 * rank + c;
            float v = tanhf(sacc + out_b[gcol]);
            d_sig[(size_t)(b0 + b) * NSTEPS * NSUB + (size_t)s * NSUB + gcol] = v;
            int di = OFF_X + (256 + gcol) * BPC + b;
#pragma unroll
            for (int r = 0; r < RANKS; r++) rb[r][di] = v;
        }
        cl.sync();
    }

    if (write_h && tid < 256) {    // final states in parity buffer 0 (NSTEPS even)
        int b = tid & 3, l64 = tid >> 2, col = RCOLS * rank + l64;
#pragma unroll
        for (int l = 0; l < 3; l++)
            d_h[((size_t)l * BATCH + (b0 + b)) * NCOND + col] = sm->h[l][0][col * BPC + b];
    }
}

// ---------------- launch ----------------
extern "C" void kernel_launch(void* const* d_in, const int* in_sizes, int n_in,
                              void* d_out, int out_size) {
    (void)n_in; (void)in_sizes;
    const float* features = (const float*)d_in[0];
    const int*   period   = (const int*)  d_in[1];
    const float* rshift   = (const float*)d_in[3];
    const float* pembed   = (const float*)d_in[4];
    const float* fd1_w = (const float*)d_in[5],  *fd1_b = (const float*)d_in[6];
    const float* c1_w  = (const float*)d_in[7],  *c1_b  = (const float*)d_in[8];
    const float* c2_w  = (const float*)d_in[9],  *c2_b  = (const float*)d_in[10];
    const float* fd2_w = (const float*)d_in[11], *fd2_b = (const float*)d_in[12];
    const float* sd1_w = (const float*)d_in[13], *sd1_b = (const float*)d_in[14];
    const float* sd2_w = (const float*)d_in[15], *sd2_b = (const float*)d_in[16];
    const float* g1_wi = (const float*)d_in[17], *g1_bi = (const float*)d_in[18];
    const float* g1_wh = (const float*)d_in[19], *g1_bh = (const float*)d_in[20];
    const float* g2_wi = (const float*)d_in[21], *g2_bi = (const float*)d_in[22];
    const float* g2_wh = (const float*)d_in[23], *g2_bh = (const float*)d_in[24];
    const float* g3_wi = (const float*)d_in[25], *g3_bi = (const float*)d_in[26];
    const float* g3_wh = (const float*)d_in[27], *g3_bh = (const float*)d_in[28];
    const float* out_w = (const float*)d_in[29], *out_b = (const float*)d_in[30];

    float* d_sig = (float*)d_out;
    const int sig_elems = BATCH * NSTEPS * NSUB;
    int write_h = (out_size >= sig_elems + 3 * BATCH * NCOND) ? 1 : 0;
    float* d_h = d_sig + sig_elems;

    prep_kernel<<<64 + 768, 256>>>(period, rshift, sd1_w, sd2_w,
                                   g1_wi, g1_wh, g2_wi, g2_wh, g3_wi, g3_wh, c1_w, c2_w);
    fd1_kernel<<<BATCH * T_IN, 256>>>(features, period, pembed, fd1_w, fd1_b);
    cond2_kernel<<<BATCH * NBF, 256>>>(c1_b, c2_b, fd2_w, fd2_b);

    const int smsz = (int)sizeof(RS);
    cudaFuncSetAttribute(rnn_kernel, cudaFuncAttributeMaxDynamicSharedMemorySize, smsz);
    rnn_kernel<<<(BATCH / BPC) * RANKS, 768, smsz>>>(sd1_b, sd2_b,
                                                     g1_bi, g1_bh, g2_bi, g2_bh, g3_bi, g3_bh,
                                                     out_w, out_b, d_sig, d_h, write_h);
}

// round 17
// speedup vs baseline: 1.2173x; 1.2173x over previous
#include <cuda_runtime.h>
#include <cuda_fp16.h>
#include <cooperative_groups.h>
#include <math.h>

namespace cg = cooperative_groups;

#define BATCH   64
#define T_IN    104
#define NFEAT   20
#define NPEMB   64
#define NCOND   256
#define NSUB    40
#define NSTEPS  400
#define NBF     100

#define RANKS   4
#define BPC     2
#define RCOLS   64

// ---------------- device scratch ----------------
static __device__ float g_t   [BATCH * T_IN * NCOND];
static __device__ float g_cond[BATCH * NBF  * NCOND];
static __device__ float g_pre [BATCH * NSTEPS * NSUB];
static __device__ float g_pim [BATCH * NSTEPS * NSUB];
static __device__ float g_w1t [NCOND * 3 * NCOND];
static __device__ float g_w2t [NCOND * 3 * NCOND];
static __device__ __half g_sd1h[376 * NCOND];
static __device__ __half g_sd2h[NCOND * NCOND];
static __device__ __half g_gw[6][NCOND * 768];

__device__ __forceinline__ float sigm(float x) { return 1.0f / (1.0f + expf(-x)); }

// ---------------- mbarrier helpers ----------------
__device__ __forceinline__ unsigned s2u(const void* p) {
    unsigned a;
    asm("{ .reg .u64 t; cvta.to.shared.u64 t, %1; cvt.u32.u64 %0, t; }" : "=r"(a) : "l"(p));
    return a;
}
__device__ __forceinline__ void bar_init(unsigned bar, unsigned cnt) {
    asm volatile("mbarrier.init.shared.b64 [%0], %1;" :: "r"(bar), "r"(cnt) : "memory");
}
// release-arrive on the same-offset barrier in every cluster CTA (incl. self)
__device__ __forceinline__ void bar_arrive_all(unsigned bar) {
#pragma unroll
    for (int r = 0; r < RANKS; r++)
        asm volatile("{ .reg .b32 ra; mapa.shared::cluster.u32 ra, %0, %1;\n\t"
                     "mbarrier.arrive.release.cluster.shared::cluster.b64 _, [ra]; }"
                     :: "r"(bar), "r"(r) : "memory");
}
__device__ __forceinline__ void bar_wait(unsigned bar, unsigned par) {
    unsigned done;
    asm volatile("{ .reg .pred p;\n\t"
                 "mbarrier.try_wait.parity.acquire.cluster.shared::cta.b64 p, [%1], %2;\n\t"
                 "selp.b32 %0, 1, 0, p; }" : "=r"(done) : "r"(bar), "r"(par) : "memory");
    if (!done) {
        asm volatile("{ .reg .pred P;\n\t"
                     "LW_%=:\n\t"
                     "mbarrier.try_wait.parity.acquire.cluster.shared::cta.b64 P, [%0], %1, 0x989680;\n\t"
                     "@P bra.uni LD_%=;\n\t"
                     "bra.uni LW_%=;\n\t"
                     "LD_%=: }" :: "r"(bar), "r"(par) : "memory");
    }
}

// ---------------- prep: fp16 weights + conv transpose + phase embedding ----------------
__global__ void prep_kernel(const int* __restrict__ period, const float* __restrict__ rshift,
                            const float* __restrict__ sd1, const float* __restrict__ sd2,
                            const float* __restrict__ a0, const float* __restrict__ a1,
                            const float* __restrict__ a2, const float* __restrict__ a3,
                            const float* __restrict__ a4, const float* __restrict__ a5,
                            const float* __restrict__ c1w, const float* __restrict__ c2w) {
    if (blockIdx.x < 64) {
        const float TWOPI = 6.28318530717958647692f;
        int b = blockIdx.x;
        __shared__ float s_cum[NBF], s_w0[NBF];
        if (threadIdx.x == 0) {
            float acc = TWOPI * rshift[b] / 160.0f;
            for (int f = 0; f < NBF; f++) {
                float w0 = TWOPI / (float)period[b * T_IN + 3 + f];
                s_w0[f] = w0; s_cum[f] = 160.0f * acc; acc += w0;
            }
        }
        __syncthreads();
        float* pre = g_pre + (size_t)b * NSTEPS * NSUB;
        float* pim = g_pim + (size_t)b * NSTEPS * NSUB;
        for (int idx = threadIdx.x; idx < NSTEPS * NSUB; idx += blockDim.x) {
            int s = idx / NSUB, j = idx - s * NSUB;
            float e = s_cum[s >> 2] + s_w0[s >> 2] * (float)((s & 3) * NSUB + j);
            double sv, cv; sincos((double)e, &sv, &cv);
            pre[idx] = (float)cv; pim[idx] = (float)sv;
        }
        return;
    }
    int i = (blockIdx.x - 64) * 256 + threadIdx.x;
    if (i < 376 * NCOND)   g_sd1h[i] = __float2half_rn(sd1[i]);
    if (i < NCOND * NCOND) g_sd2h[i] = __float2half_rn(sd2[i]);
    if (i < NCOND * 768) {
        g_gw[0][i] = __float2half_rn(a0[i]); g_gw[1][i] = __float2half_rn(a1[i]);
        g_gw[2][i] = __float2half_rn(a2[i]); g_gw[3][i] = __float2half_rn(a3[i]);
        g_gw[4][i] = __float2half_rn(a4[i]); g_gw[5][i] = __float2half_rn(a5[i]);
    }
    if (i < NCOND * NCOND * 3) {
        int o = i / (NCOND * 3), r = i - o * (NCOND * 3);
        g_w1t[r * NCOND + o] = c1w[i];
        g_w2t[r * NCOND + o] = c2w[i];
    }
}

// ---------------- fd1 ----------------
__global__ void fd1_kernel(const float* __restrict__ feat, const int* __restrict__ period,
                           const float* __restrict__ pemb, const float* __restrict__ w,
                           const float* __restrict__ bias) {
    int bt = blockIdx.x, tid = threadIdx.x;
    __shared__ float xs[NFEAT + NPEMB];
    if (tid < NFEAT)              xs[tid] = feat[(size_t)bt * NFEAT + tid];
    else if (tid < NFEAT + NPEMB) xs[tid] = pemb[(size_t)period[bt] * NPEMB + (tid - NFEAT)];
    __syncthreads();
    float acc = bias[tid];
#pragma unroll 4
    for (int k = 0; k < NFEAT + NPEMB; k++)
        acc = fmaf(xs[k], w[(size_t)k * NCOND + tid], acc);
    g_t[(size_t)bt * NCOND + tid] = tanhf(acc);
}

// ---------------- cond2: fused conv1+conv2+fd2 ----------------
__global__ void cond2_kernel(const float* __restrict__ c1b, const float* __restrict__ c2b,
                             const float* __restrict__ fd2w, const float* __restrict__ fd2b) {
    int bf = blockIdx.x;
    int b = bf / NBF, f = bf - b * NBF;
    int tid = threadIdx.x;
    __shared__ float xs[5][NCOND], c1s[3][NCOND], c2s[NCOND];
#pragma unroll
    for (int d = 0; d < 5; d++)
        xs[d][tid] = g_t[((size_t)(b * T_IN + f + d)) * NCOND + tid];
    __syncthreads();
    float a0 = c1b[tid], a1 = a0, a2 = a0;
    for (int i = 0; i < NCOND; i++) {
#pragma unroll
        for (int d = 0; d < 3; d++) {
            float w = g_w1t[(size_t)(i * 3 + d) * NCOND + tid];
            a0 = fmaf(xs[d][i],     w, a0);
            a1 = fmaf(xs[d + 1][i], w, a1);
            a2 = fmaf(xs[d + 2][i], w, a2);
        }
    }
    c1s[0][tid] = tanhf(a0); c1s[1][tid] = tanhf(a1); c1s[2][tid] = tanhf(a2);
    __syncthreads();
    float acc = c2b[tid];
    for (int i = 0; i < NCOND; i++) {
#pragma unroll
        for (int d = 0; d < 3; d++)
            acc = fmaf(c1s[d][i], g_w2t[(size_t)(i * 3 + d) * NCOND + tid], acc);
    }
    c2s[tid] = tanhf(acc);
    __syncthreads();
    acc = fd2b[tid];
#pragma unroll 4
    for (int k = 0; k < NCOND; k++)
        acc = fmaf(c2s[k], fd2w[(size_t)k * NCOND + tid], acc);
    g_cond[(size_t)bf * NCOND + tid] = tanhf(acc);
}

// ======================= rnn: R13 skeleton + per-phase mbarriers =======================
// 32 clusters x 4 CTAs (128 SMs), BPC=2, fp16 weights. Phase barriers bar[0..4]
// (sd1,sd2,g1,g2,g3); writers release-arrive on all 4 ranks; consumers acquire-wait,
// EXCEPT warps whose K-slice is rank-local (skip). gh matvecs read prev-step h
// (fenced by the one per-step cluster.sync at the out phase). h double-buffered.
struct RnnSmem {
    float4 part4[24][32];
    float  x2 [376 * BPC];
    float  tta[NCOND * BPC];
    float  ttb[NCOND * BPC];
    float  hbi[3][2][NCOND * BPC];
    float  gil[3][RCOLS * BPC];
    float  ghl[3][RCOLS * BPC];
};

__device__ __forceinline__ void gru_layer(
    const __half* __restrict__ wi, const float* __restrict__ bi,
    const __half* __restrict__ wh, const float* __restrict__ bh,
    const float* xv, const float* hold, int hnew_off,
    unsigned bar_prev, unsigned bar_self, unsigned par,
    RnnSmem* sm, float* const* rb, int rank, int tid)
{
    {
        int wid = tid >> 5, lane = tid & 31;
        int hf = wid >= 12;
        int w12 = wid - 12 * hf;
        int t = w12 >> 2, ks = w12 & 3;
        if (!hf && ks != rank) bar_wait(bar_prev, par);   // gi needs same-step xv slice
        const __half* Wp = (hf ? wh : wi) + 256 * t + RCOLS * rank + 2 * lane;
        const float*  v  = hf ? hold : xv;                // gh: prev-step h, step-fenced
        float a00 = 0.f, a01 = 0.f, a10 = 0.f, a11 = 0.f;
        int k0 = ks * 64;
#pragma unroll 8
        for (int k = k0; k < k0 + 64; k++) {
            float2 w2 = __half22float2(*(const __half2*)(Wp + (size_t)k * 768));
            float2 xk = *(const float2*)(v + 2 * k);
            a00 = fmaf(w2.x, xk.x, a00); a01 = fmaf(w2.x, xk.y, a01);
            a10 = fmaf(w2.y, xk.x, a10); a11 = fmaf(w2.y, xk.y, a11);
        }
        sm->part4[wid][lane] = make_float4(a00, a01, a10, a11);
    }
    __syncthreads();
    {
        int e = tid;
        int b   = e & 1;  e >>= 1;
        int c01 = e & 1;  e >>= 1;
        int ln  = e & 31; e >>= 5;
        int t   = e % 3, hf = e / 3;
        const float* pf = (const float*)&sm->part4[0][0];
        int base = (hf * 3 + t) * 4;
        int comp = ln * 4 + c01 * 2 + b;
        float s = pf[(base + 0) * 128 + comp] + pf[(base + 1) * 128 + comp]
                + pf[(base + 2) * 128 + comp] + pf[(base + 3) * 128 + comp];
        int l64 = 2 * ln + c01;
        s += (hf ? bh : bi)[256 * t + RCOLS * rank + l64];
        (hf ? sm->ghl : sm->gil)[t][l64 * BPC + b] = s;
    }
    __syncthreads();
    if (tid < 128) {
        int b = tid & 1, l = tid >> 1;
        int li = l * BPC + b;
        int ci = (RCOLS * rank + l) * BPC + b;
        float rg = sigm(sm->gil[0][li] + sm->ghl[0][li]);
        float zg = sigm(sm->gil[1][li] + sm->ghl[1][li]);
        float ng = tanhf(fmaf(rg, sm->ghl[2][li], sm->gil[2][li]));
        float hv = fmaf(zg, hold[ci] - ng, ng);
        int di = hnew_off + ci;
#pragma unroll
        for (int r = 0; r < RANKS; r++) rb[r][di] = hv;
        bar_arrive_all(bar_self);
    }
    __syncthreads();
}

__global__ void __cluster_dims__(RANKS, 1, 1) __launch_bounds__(768, 1) rnn_kernel(
    const float* __restrict__ sd1_b, const float* __restrict__ sd2_b,
    const float* __restrict__ g1_bi, const float* __restrict__ g1_bh,
    const float* __restrict__ g2_bi, const float* __restrict__ g2_bh,
    const float* __restrict__ g3_bi, const float* __restrict__ g3_bh,
    const float* __restrict__ out_w, const float* __restrict__ out_b,
    float* __restrict__ d_sig, float* __restrict__ d_h, int write_h)
{
    static __shared__ RnnSmem sm;
    __shared__ unsigned long long bars[5];
    cg::cluster_group cl = cg::this_cluster();
    const int rank = (int)cl.block_rank();
    const int b0   = (blockIdx.x / RANKS) * BPC;
    const int tid  = threadIdx.x;

    float* base = (float*)&sm;
    float* rb[RANKS];
#pragma unroll
    for (int r = 0; r < RANKS; r++) rb[r] = (float*)cl.map_shared_rank(&sm, r);
    const int OFF_X  = (int)(sm.x2  - base);
    const int OFF_TA = (int)(sm.tta - base);
    const int OFF_TB = (int)(sm.ttb - base);
    const int OFF_HB = (int)(&sm.hbi[0][0][0] - base);
    const int HB_L   = 2 * NCOND * BPC;
    const int HB_P   = NCOND * BPC;
    unsigned bar[5];
#pragma unroll
    for (int i = 0; i < 5; i++) bar[i] = s2u(&bars[i]);
    if (tid == 0)
        for (int i = 0; i < 5; i++) bar_init(bar[i], 512);   // 4 CTAs x 128 writers

    for (int i = tid; i < 3 * 2 * NCOND * BPC; i += 768) (&sm.hbi[0][0][0])[i] = 0.f;
    for (int i = tid; i < NSUB * BPC; i += 768) sm.x2[(256 + i / BPC) * BPC + (i & 1)] = 0.f;
    cl.sync();   // bars + init visible cluster-wide

    for (int s = 0; s < NSTEPS; s++) {
        const int p = s & 1;
        const unsigned par = (unsigned)p;
        // refill (local; prev arrived via out bcast, fenced by out cluster.sync)
        for (int i = tid; i < 256 * BPC; i += 768) {
            int b = i & 1, c = i >> 1;
            sm.x2[c * BPC + b] = g_cond[((size_t)(b0 + b) * NBF + (s >> 2)) * NCOND + c];
        }
        for (int i = tid; i < 80 * BPC; i += 768) {
            int b = i & 1, j = i >> 1;
            sm.x2[(296 + j) * BPC + b] = (j < NSUB)
                ? g_pre[(size_t)(b0 + b) * NSTEPS * NSUB + s * NSUB + j]
                : g_pim[(size_t)(b0 + b) * NSTEPS * NSUB + s * NSUB + (j - NSUB)];
        }
        __syncthreads();

        // ---- P0: sd1 (inputs all local/step-fenced -> no wait), 24-way ksplit ----
        {
            int lane = tid & 31, ks = tid >> 5;
            const __half* Wp = g_sd1h + RCOLS * rank + 2 * lane;
            float a00 = 0.f, a01 = 0.f, a10 = 0.f, a11 = 0.f;
            int k0 = ks * 16, k1 = k0 + 16; if (k1 > 376) k1 = 376;
#pragma unroll 8
            for (int k = k0; k < k1; k++) {
                float2 w2 = __half22float2(*(const __half2*)(Wp + (size_t)k * NCOND));
                float2 xk = *(const float2*)(sm.x2 + 2 * k);
                a00 = fmaf(w2.x, xk.x, a00); a01 = fmaf(w2.x, xk.y, a01);
                a10 = fmaf(w2.y, xk.x, a10); a11 = fmaf(w2.y, xk.y, a11);
            }
            sm.part4[ks][lane] = make_float4(a00, a01, a10, a11);
        }
        __syncthreads();
        if (tid < 128) {
            int b = tid & 1, c01 = (tid >> 1) & 1, ln = tid >> 2;
            const float* pf = (const float*)&sm.part4[0][0];
            int comp = ln * 4 + c01 * 2 + b;
            float sv = 0.f;
#pragma unroll
            for (int kk = 0; kk < 24; kk++) sv += pf[kk * 128 + comp];
            int l64 = 2 * ln + c01;
            float v = tanhf(sv + sd1_b[RCOLS * rank + l64]);
            int di = OFF_TA + (RCOLS * rank + l64) * BPC + b;
#pragma unroll
            for (int r = 0; r < RANKS; r++) rb[r][di] = v;
            bar_arrive_all(bar[0]);
        }
        __syncthreads();

        // ---- P1: sd2 (rank-aligned 4x6 ksplit; own slice skips wait) ----
        {
            int lane = tid & 31, wid = tid >> 5;
            int ks4 = wid / 6, sub = wid - 6 * ks4;
            if (ks4 != rank) bar_wait(bar[0], par);
            const __half* Wp = g_sd2h + RCOLS * rank + 2 * lane;
            float a00 = 0.f, a01 = 0.f, a10 = 0.f, a11 = 0.f;
            int k0 = ks4 * 64 + sub * 11, k1 = k0 + 11;
            int kend = ks4 * 64 + 64; if (k1 > kend) k1 = kend;
            for (int k = k0; k < k1; k++) {
                float2 w2 = __half22float2(*(const __half2*)(Wp + (size_t)k * NCOND));
                float2 xk = *(const float2*)(sm.tta + 2 * k);
                a00 = fmaf(w2.x, xk.x, a00); a01 = fmaf(w2.x, xk.y, a01);
                a10 = fmaf(w2.y, xk.x, a10); a11 = fmaf(w2.y, xk.y, a11);
            }
            sm.part4[wid][lane] = make_float4(a00, a01, a10, a11);
        }
        __syncthreads();
        if (tid < 128) {
            int b = tid & 1, c01 = (tid >> 1) & 1, ln = tid >> 2;
            const float* pf = (const float*)&sm.part4[0][0];
            int comp = ln * 4 + c01 * 2 + b;
            float sv = 0.f;
#pragma unroll
            for (int kk = 0; kk < 24; kk++) sv += pf[kk * 128 + comp];
            int l64 = 2 * ln + c01;
            float v = tanhf(sv + sd2_b[RCOLS * rank + l64]);
            int di = OFF_TB + (RCOLS * rank + l64) * BPC + b;
#pragma unroll
            for (int r = 0; r < RANKS; r++) rb[r][di] = v;
            bar_arrive_all(bar[1]);
        }
        __syncthreads();

        // ---- P2..P4: GRUs ----
        gru_layer(g_gw[0], g1_bi, g_gw[1], g1_bh, sm.ttb,           sm.hbi[0][p],
                  OFF_HB + 0 * HB_L + (p ^ 1) * HB_P, bar[1], bar[2], par, &sm, rb, rank, tid);
        gru_layer(g_gw[2], g2_bi, g_gw[3], g2_bh, sm.hbi[0][p ^ 1], sm.hbi[1][p],
                  OFF_HB + 1 * HB_L + (p ^ 1) * HB_P, bar[2], bar[3], par, &sm, rb, rank, tid);
        gru_layer(g_gw[4], g3_bi, g_gw[5], g3_bh, sm.hbi[1][p ^ 1], sm.hbi[2][p],
                  OFF_HB + 2 * HB_L + (p ^ 1) * HB_P, bar[3], bar[4], par, &sm, rb, rank, tid);

        // ---- P5: out (wait bar4 unless K-slice is own) + step cluster.sync ----
        const float* h3 = sm.hbi[2][p ^ 1];
        float* pf = (float*)&sm.part4[0][0];
        if (tid < 640) {
            int b = tid & 1, c = (tid >> 1) % 10, ks = tid / 20;
            if ((ks >> 3) != rank) bar_wait(bar[4], par);
            const float* Wp = out_w + 10 * rank + c;
            float a = 0.f;
            int k0 = ks * 8;
#pragma unroll
            for (int k = k0; k < k0 + 8; k++)
                a = fmaf(Wp[k * NSUB], h3[k * BPC + b], a);
            pf[tid] = a;
        }
        __syncthreads();
        if (tid < 20) {
            int b = tid & 1, c = tid >> 1;
            float sacc = 0.f;
#pragma unroll
            for (int ks = 0; ks < 32; ks++) sacc += pf[ks * 20 + tid];
            int gcol = 10 * rank + c;
            float v = tanhf(sacc + out_b[gcol]);
            d_sig[(size_t)(b0 + b) * NSTEPS * NSUB + (size_t)s * NSUB + gcol] = v;
            int di = OFF_X + (256 + gcol) * BPC + b;
#pragma unroll
            for (int r = 0; r < RANKS; r++) rb[r][di] = v;
        }
        cl.sync();   // per-step fence: bounds skew, covers prev/h visibility
    }

    if (write_h && tid < 128) {
        int b = tid & 1, l64 = tid >> 1, col = RCOLS * rank + l64;
#pragma unroll
        for (int l = 0; l < 3; l++)
            d_h[((size_t)l * BATCH + (b0 + b)) * NCOND + col] = sm.hbi[l][0][col * BPC + b];
    }
}

// ---------------- launch ----------------
extern "C" void kernel_launch(void* const* d_in, const int* in_sizes, int n_in,
                              void* d_out, int out_size) {
    (void)n_in; (void)in_sizes;
    const float* features = (const float*)d_in[0];
    const int*   period   = (const int*)  d_in[1];
    const float* rshift   = (const float*)d_in[3];
    const float* pembed   = (const float*)d_in[4];
    const float* fd1_w = (const float*)d_in[5],  *fd1_b = (const float*)d_in[6];
    const float* c1_w  = (const float*)d_in[7],  *c1_b  = (const float*)d_in[8];
    const float* c2_w  = (const float*)d_in[9],  *c2_b  = (const float*)d_in[10];
    const float* fd2_w = (const float*)d_in[11], *fd2_b = (const float*)d_in[12];
    const float* sd1_w = (const float*)d_in[13], *sd1_b = (const float*)d_in[14];
    const float* sd2_w = (const float*)d_in[15], *sd2_b = (const float*)d_in[16];
    const float* g1_wi = (const float*)d_in[17], *g1_bi = (const float*)d_in[18];
    const float* g1_wh = (const float*)d_in[19], *g1_bh = (const float*)d_in[20];
    const float* g2_wi = (const float*)d_in[21], *g2_bi = (const float*)d_in[22];
    const float* g2_wh = (const float*)d_in[23], *g2_bh = (const float*)d_in[24];
    const float* g3_wi = (const float*)d_in[25], *g3_bi = (const float*)d_in[26];
    const float* g3_wh = (const float*)d_in[27], *g3_bh = (const float*)d_in[28];
    const float* out_w = (const float*)d_in[29], *out_b = (const float*)d_in[30];

    float* d_sig = (float*)d_out;
    const int sig_elems = BATCH * NSTEPS * NSUB;
    int write_h = (out_size >= sig_elems + 3 * BATCH * NCOND) ? 1 : 0;
    float* d_h = d_sig + sig_elems;

    prep_kernel<<<64 + 768, 256>>>(period, rshift, sd1_w, sd2_w,
                                   g1_wi, g1_wh, g2_wi, g2_wh, g3_wi, g3_wh, c1_w, c2_w);
    fd1_kernel<<<BATCH * T_IN, 256>>>(features, period, pembed, fd1_w, fd1_b);
    cond2_kernel<<<BATCH * NBF, 256>>>(c1_b, c2_b, fd2_w, fd2_b);
    rnn_kernel<<<(BATCH / BPC) * RANKS, 768>>>(sd1_b, sd2_b,
                                               g1_bi, g1_bh, g2_bi, g2_bh, g3_bi, g3_bh,
                                               out_w, out_b, d_sig, d_h, write_h);
}